// round 17
// baseline (speedup 1.0000x reference)
#include <cuda_runtime.h>
#include <cstdint>

#define BETA 0.95f
#define MB 512
#define L1N 2048
#define L2N 2048
#define L3N 512
#define K1IN 1024
#define TSTEPS 16

#define NM2 (L2N * MB)
#define NM3 (L3N * MB)

// ---------------- scratch ----------------
__device__ float g_xT [K1IN * MB];             // xT [k][m]
__device__ float g_w1T[K1IN * L1N];            // W1T[k][n]
__device__ float g_w2T[L1N * L2N];             // W2T[k][n]
__device__ float g_w3T[L2N * L3N];             // W3T[k][n]
__device__ float g_c1T[L1N * MB];              // c1T[n][m]
__device__ float g_s1 [TSTEPS * NM2];          // s1 [t][k][m]
__device__ float g_C2 [TSTEPS * NM2];          // C2 [t][n][m] (becomes s2 in-place)
__device__ float g_C3 [TSTEPS * NM3];          // C3 [t][n][m]

// packed f32x2: per-lane IEEE fp32 FMA (RN) -> bit-exact vs FFMA
#define FMA2(d, a, b) \
    asm("fma.rn.f32x2 %0, %1, %2, %0;" : "+l"(d) : "l"(a), "l"(b))
#define PACK2(d, x) \
    asm("mov.b64 %0, {%1, %1};" : "=l"(d) : "f"(x))
#define UNPACK2(lo, hi, v) \
    asm("mov.b64 {%0, %1}, %2;" : "=f"(lo), "=f"(hi) : "l"(v))

// ---------------- transpose ----------------
__global__ void transpose_k(const float* __restrict__ src, float* __restrict__ dst,
                            int R, int C) {
    __shared__ float t[32][33];
    const int c0 = blockIdx.x * 32, r0 = blockIdx.y * 32;
    for (int j = threadIdx.y; j < 32; j += 8)
        t[j][threadIdx.x] = src[(size_t)(r0 + j) * C + c0 + threadIdx.x];
    __syncthreads();
    for (int j = threadIdx.y; j < 32; j += 8)
        dst[(size_t)(c0 + j) * R + r0 + threadIdx.x] = t[threadIdx.x][j];
}

// ---- layer-1: closed-form 16-step LIF on static current ----
__global__ void sim_layer1() {
    int i = blockIdx.x * blockDim.x + threadIdx.x;   // over c1T [n][m]
    float c = g_c1T[i];
    float m = 0.0f;
#pragma unroll
    for (int t = 0; t < TSTEPS; t++) {
        m = BETA * m + c;
        float s = (m > 1.0f) ? 1.0f : 0.0f;
        m -= s;
        g_s1[t * NM2 + i] = s;
    }
}

// ---------------- batched fp32x2 GEMM, 128x128 tile (bit-exact ascending-k) ----------------
// 256 threads, per-thread 8m (4 packed pairs) x 8n. BK=16, double-buffered smem.
// A matrices are [K][512] per t-chunk of 512 rows; m_eff = tch*512 + mloc.
// MODE 0: out[tch][n*512+m] = acc + bias[n]
// MODE 1: out[tch][n*512+m] = acc          (bias applied in recurrence kernels)
template <int MODE>
__global__ void __launch_bounds__(256, 2) gemmB(
    const float* __restrict__ A, size_t chunkA,
    const float* __restrict__ BT, int Ntot,
    const float* __restrict__ bias,
    float* __restrict__ outp, size_t chunkOut,
    int K, int nbx, int ntiles)
{
    __shared__ __align__(16) float As[2 * 16 * 128];   // 16 KB
    __shared__ __align__(16) float Bs[2 * 16 * 128];   // 16 KB

    const int tid = threadIdx.x;
    const int lk = tid >> 5;             // + i*8   (tile rows: 16 k x 128 cols)
    const int lc = (tid & 31) * 4;
    const int tx = tid & 15;             // n: 8 cols each
    const int ty = tid >> 4;             // m: 8 rows each (4 packed pairs)

    for (int tile = blockIdx.x; tile < ntiles; tile += gridDim.x) {
        const int m0 = (tile / nbx) * 128;
        const int n0 = (tile % nbx) * 128;
        const int tch = m0 >> 9;
        const int mloc = m0 & 511;
        const float* Ab = A + (size_t)tch * chunkA + mloc;
        float* Ob = outp + (size_t)tch * chunkOut + mloc;

        uint64_t acc2[4][8];
#pragma unroll
        for (int i = 0; i < 4; i++)
#pragma unroll
            for (int j = 0; j < 8; j++) acc2[i][j] = 0ull;

        float4 pa[2], pb[2];
        const int niter = K >> 4;        // BK = 16

        // prologue: tile 0 -> regs -> buffer 0
#pragma unroll
        for (int i = 0; i < 2; i++) {
            pa[i] = *reinterpret_cast<const float4*>(Ab + (size_t)(lk + i * 8) * 512 + lc);
            pb[i] = *reinterpret_cast<const float4*>(BT + (size_t)(lk + i * 8) * Ntot + n0 + lc);
        }
#pragma unroll
        for (int i = 0; i < 2; i++) {
            *reinterpret_cast<float4*>(As + (lk + i * 8) * 128 + lc) = pa[i];
            *reinterpret_cast<float4*>(Bs + (lk + i * 8) * 128 + lc) = pb[i];
        }

        for (int it = 0; it < niter; it++) {
            const int b = it & 1;
            __syncthreads();

            const bool more = (it + 1 < niter);
            if (more) {
                const int k0 = (it + 1) * 16;
#pragma unroll
                for (int i = 0; i < 2; i++) {
                    pa[i] = *reinterpret_cast<const float4*>(Ab + (size_t)(k0 + lk + i * 8) * 512 + lc);
                    pb[i] = *reinterpret_cast<const float4*>(BT + (size_t)(k0 + lk + i * 8) * Ntot + n0 + lc);
                }
            }

            float* Abuf = As + b * (16 * 128);
            float* Bbuf = Bs + b * (16 * 128);
#pragma unroll
            for (int k = 0; k < 16; k++) {
                ulonglong2 a01 = *reinterpret_cast<const ulonglong2*>(Abuf + k * 128 + ty * 8);
                ulonglong2 a23 = *reinterpret_cast<const ulonglong2*>(Abuf + k * 128 + ty * 8 + 4);
                float4 w0 = *reinterpret_cast<const float4*>(Bbuf + k * 128 + tx * 8);
                float4 w1 = *reinterpret_cast<const float4*>(Bbuf + k * 128 + tx * 8 + 4);
                float ws[8] = { w0.x, w0.y, w0.z, w0.w, w1.x, w1.y, w1.z, w1.w };
#pragma unroll
                for (int j = 0; j < 8; j++) {
                    uint64_t br;
                    PACK2(br, ws[j]);
                    FMA2(acc2[0][j], a01.x, br);
                    FMA2(acc2[1][j], a01.y, br);
                    FMA2(acc2[2][j], a23.x, br);
                    FMA2(acc2[3][j], a23.y, br);
                }
            }

            if (more) {
                const int nb = b ^ 1;
                float* Ad = As + nb * (16 * 128);
                float* Bd = Bs + nb * (16 * 128);
#pragma unroll
                for (int i = 0; i < 2; i++) {
                    *reinterpret_cast<float4*>(Ad + (lk + i * 8) * 128 + lc) = pa[i];
                    *reinterpret_cast<float4*>(Bd + (lk + i * 8) * 128 + lc) = pb[i];
                }
            }
        }

        // ---- epilogue ----
#pragma unroll
        for (int j = 0; j < 8; j++) {
            const int n = n0 + tx * 8 + j;
            float vv[8];
            UNPACK2(vv[0], vv[1], acc2[0][j]);
            UNPACK2(vv[2], vv[3], acc2[1][j]);
            UNPACK2(vv[4], vv[5], acc2[2][j]);
            UNPACK2(vv[6], vv[7], acc2[3][j]);
            if (MODE == 0) {
                const float bj = bias[n];
#pragma unroll
                for (int h = 0; h < 8; h++) vv[h] += bj;
            }
            float* dst = Ob + (size_t)n * 512 + ty * 8;
            float4 o0, o1;
            o0.x = vv[0]; o0.y = vv[1]; o0.z = vv[2]; o0.w = vv[3];
            o1.x = vv[4]; o1.y = vv[5]; o1.z = vv[6]; o1.w = vv[7];
            *reinterpret_cast<float4*>(dst) = o0;
            *reinterpret_cast<float4*>(dst + 4) = o1;
        }
    }
}

// ---- layer-2 recurrence (float4): membranes in registers, spikes in-place ----
__global__ void rec2(const float* __restrict__ b2) {
    int i4 = blockIdx.x * blockDim.x + threadIdx.x;   // float4 index over [n][m]
    const int base = i4 * 4;
    const float bj = b2[base >> 9];                   // 512 % 4 == 0 -> same n for all 4
    float mm[4] = {0.0f, 0.0f, 0.0f, 0.0f};
    float4* C2v = reinterpret_cast<float4*>(g_C2);
#pragma unroll
    for (int t = 0; t < TSTEPS; t++) {
        float4 c = C2v[t * (NM2 / 4) + i4];
        float cv[4] = { c.x, c.y, c.z, c.w };
        float sv[4];
#pragma unroll
        for (int h = 0; h < 4; h++) {
            float v = cv[h] + bj;
            float m2 = BETA * mm[h] + v;
            float s = (m2 > 1.0f) ? 1.0f : 0.0f;
            mm[h] = m2 - s;
            sv[h] = s;
        }
        float4 o; o.x = sv[0]; o.y = sv[1]; o.z = sv[2]; o.w = sv[3];
        C2v[t * (NM2 / 4) + i4] = o;
    }
}

// ---- layer-3 recurrence + output sum (float4 loads) ----
__global__ void rec3(const float* __restrict__ b3, float* __restrict__ out) {
    int i4 = blockIdx.x * blockDim.x + threadIdx.x;   // float4 index over [n][m]
    const int base = i4 * 4;
    const int n = base >> 9, m = base & 511;
    const float bj = b3[n];
    float mm[4] = {0.0f, 0.0f, 0.0f, 0.0f};
    float sum[4] = {0.0f, 0.0f, 0.0f, 0.0f};
    const float4* C3v = reinterpret_cast<const float4*>(g_C3);
#pragma unroll
    for (int t = 0; t < TSTEPS; t++) {
        float4 c = C3v[t * (NM3 / 4) + i4];
        float cv[4] = { c.x, c.y, c.z, c.w };
#pragma unroll
        for (int h = 0; h < 4; h++) {
            float v = cv[h] + bj;
            float m3 = BETA * mm[h] + v;
            float s = (m3 > 1.0f) ? 1.0f : 0.0f;
            mm[h] = m3 - s;
            sum[h] += s;
        }
    }
#pragma unroll
    for (int h = 0; h < 4; h++)
        out[(size_t)(m + h) * L3N + n] = sum[h];
}

// ---------------- host ----------------
extern "C" void kernel_launch(void* const* d_in, const int* in_sizes, int n_in,
                              void* d_out, int out_size)
{
    const float* x  = (const float*)d_in[0];
    const float* W1 = (const float*)d_in[1];
    const float* b1 = (const float*)d_in[2];
    const float* W2 = (const float*)d_in[3];
    const float* b2 = (const float*)d_in[4];
    const float* W3 = (const float*)d_in[5];
    const float* b3 = (const float*)d_in[6];
    float* out = (float*)d_out;

    float *xT, *w1T, *w2T, *w3T, *c1T, *s1, *C2, *C3;
    cudaGetSymbolAddress((void**)&xT,  g_xT);
    cudaGetSymbolAddress((void**)&w1T, g_w1T);
    cudaGetSymbolAddress((void**)&w2T, g_w2T);
    cudaGetSymbolAddress((void**)&w3T, g_w3T);
    cudaGetSymbolAddress((void**)&c1T, g_c1T);
    cudaGetSymbolAddress((void**)&s1,  g_s1);
    cudaGetSymbolAddress((void**)&C2,  g_C2);
    cudaGetSymbolAddress((void**)&C3,  g_C3);

    dim3 tb(32, 8);
    transpose_k<<<dim3(K1IN / 32, MB  / 32), tb>>>(x,  xT,  MB,  K1IN);
    transpose_k<<<dim3(K1IN / 32, L1N / 32), tb>>>(W1, w1T, L1N, K1IN);
    transpose_k<<<dim3(L1N  / 32, L2N / 32), tb>>>(W2, w2T, L2N, L1N);
    transpose_k<<<dim3(L2N  / 32, L3N / 32), tb>>>(W3, w3T, L3N, L2N);

    // layer-1 current, once: c1T = (x @ W1^T + b1)^T   (4 x 16 = 64 tiles)
    gemmB<0><<<64, 256>>>(xT, 0, w1T, L1N, b1, c1T, 0, K1IN, 16, 64);

    // 16-step layer-1 spike trains
    sim_layer1<<<NM2 / 256, 256>>>();

    // batched layer-2 GEMM: 64 x 16 = 1024 tiles, 1 tile/CTA
    gemmB<1><<<1024, 256>>>(s1, (size_t)NM2, w2T, L2N, nullptr,
                            C2, (size_t)NM2, L1N, 16, 1024);

    // layer-2 membrane recurrence (float4), spikes in-place
    rec2<<<NM2 / 4 / 256, 256>>>(b2);

    // batched layer-3 GEMM: 64 x 4 = 256 tiles, 1 tile/CTA (single wave)
    gemmB<1><<<256, 256>>>(C2, (size_t)NM2, w3T, L3N, nullptr,
                           C3, (size_t)NM3, L2N, 4, 256);

    // layer-3 recurrence + spike-count sum -> out (float4 loads)
    rec3<<<NM3 / 4 / 256, 256>>>(b3, out);
}